// round 2
// baseline (speedup 1.0000x reference)
#include <cuda_runtime.h>

#define NTOK 65536
#define KCB  8192
#define DDIM 64
#define DECAYF 0.9f
#define EPSF 1e-5f

// ---- scratch (no allocation allowed) ----
__device__ float g_cnorm[KCB];
__device__ int   g_token[NTOK];
__device__ float g_counts[KCB];
__device__ float g_embed_sum[KCB * DDIM];
__device__ float g_qerr;
__device__ float g_nsum;

// ---------------- zero scratch ----------------
__global__ void k_zero() {
    int i = blockIdx.x * blockDim.x + threadIdx.x;
    if (i < KCB * DDIM) g_embed_sum[i] = 0.0f;
    if (i < KCB)        g_counts[i]    = 0.0f;
    if (i == 0) { g_qerr = 0.0f; g_nsum = 0.0f; }
}

// ---------------- codebook norms: warp per code ----------------
__global__ void k_cnorm(const float* __restrict__ w) {
    int warp = (blockIdx.x * blockDim.x + threadIdx.x) >> 5;
    int lane = threadIdx.x & 31;
    if (warp >= KCB) return;
    float v0 = w[warp * DDIM + lane];
    float v1 = w[warp * DDIM + 32 + lane];
    float s = v0 * v0 + v1 * v1;
    #pragma unroll
    for (int o = 16; o; o >>= 1) s += __shfl_xor_sync(0xffffffffu, s, o);
    if (lane == 0) g_cnorm[warp] = s;
}

// ---------------- fused GEMM + argmin ----------------
// Block: 64 tokens x full K. Chunk: 128 codes.
// 128 threads: tx = tid&7 -> 8 token-groups of 8 tokens (4 f32x2 pairs),
//              ty = tid>>3 -> 16 code-groups of 8 codes.
static constexpr int BT  = 64;
static constexpr int CC  = 128;
static constexpr int TPB = 128;
static constexpr int SMEM_MAIN = DDIM * BT * 4 + DDIM * CC * 8 + CC * 4; // 82432

__device__ __forceinline__ unsigned long long ffma2(
    unsigned long long a, unsigned long long b, unsigned long long c) {
    unsigned long long d;
    asm("fma.rn.f32x2 %0, %1, %2, %3;" : "=l"(d) : "l"(a), "l"(b), "l"(c));
    return d;
}

__global__ __launch_bounds__(TPB) void k_main(const float* __restrict__ z,
                                              const float* __restrict__ w) {
    extern __shared__ float smem[];
    float* zs = smem;                                                    // [64][BT]
    unsigned long long* wsd = (unsigned long long*)(smem + DDIM * BT);   // [64][CC] (w,w) pairs
    float* cns = (float*)(wsd + DDIM * CC);                              // [CC]

    const int tid  = threadIdx.x;
    const int tx   = tid & 7;
    const int ty   = tid >> 3;
    const int tok0 = blockIdx.x * BT;

    // Load z tile transposed: zs[d][t]
    for (int i = tid; i < BT * DDIM; i += TPB) {
        int t = i >> 6, d = i & 63;
        zs[d * BT + t] = z[(size_t)(tok0 + t) * DDIM + d];
    }

    float bestv[8];
    int   besti[8];
    #pragma unroll
    for (int t = 0; t < 8; t++) { bestv[t] = 3.4e38f; besti[t] = 0; }

    for (int cb = 0; cb < KCB; cb += CC) {
        __syncthreads();
        // Load w chunk, duplicated into f32x2 pairs: wsd[d][c] = (w, w)
        for (int i = tid; i < CC * DDIM; i += TPB) {
            int c = i >> 6, d = i & 63;
            unsigned int u = __float_as_uint(w[(size_t)(cb + c) * DDIM + d]);
            wsd[d * CC + c] = ((unsigned long long)u << 32) | (unsigned long long)u;
        }
        if (tid < CC) cns[tid] = g_cnorm[cb + tid];
        __syncthreads();

        unsigned long long acc[4][8];
        #pragma unroll
        for (int i = 0; i < 4; i++)
            #pragma unroll
            for (int j = 0; j < 8; j++) acc[i][j] = 0ull;

        const float* zrow = zs + tx * 8;
        const unsigned long long* wrow = wsd + ty * 8;

        #pragma unroll 8
        for (int d = 0; d < DDIM; d++) {
            ulonglong2 za = *(const ulonglong2*)(zrow + (size_t)d * BT);
            ulonglong2 zb = *(const ulonglong2*)(zrow + (size_t)d * BT + 4);
            ulonglong2 w0 = *(const ulonglong2*)(wrow + (size_t)d * CC);
            ulonglong2 w1 = *(const ulonglong2*)(wrow + (size_t)d * CC + 2);
            ulonglong2 w2 = *(const ulonglong2*)(wrow + (size_t)d * CC + 4);
            ulonglong2 w3 = *(const ulonglong2*)(wrow + (size_t)d * CC + 6);
            unsigned long long zp[4] = {za.x, za.y, zb.x, zb.y};
            unsigned long long wp[8] = {w0.x, w0.y, w1.x, w1.y, w2.x, w2.y, w3.x, w3.y};
            #pragma unroll
            for (int i = 0; i < 4; i++)
                #pragma unroll
                for (int j = 0; j < 8; j++)
                    acc[i][j] = ffma2(zp[i], wp[j], acc[i][j]);
        }

        float cn[8];
        #pragma unroll
        for (int j = 0; j < 8; j++) cn[j] = cns[ty * 8 + j];

        // dist' = ||c||^2 - 2 z.c  (||z||^2 dropped: constant per token)
        #pragma unroll
        for (int i = 0; i < 4; i++) {
            #pragma unroll
            for (int j = 0; j < 8; j++) {
                float lo = __uint_as_float((unsigned int)(acc[i][j] & 0xffffffffu));
                float hi = __uint_as_float((unsigned int)(acc[i][j] >> 32));
                int ci = cb + ty * 8 + j;
                float d0 = fmaf(-2.0f, lo, cn[j]);
                float d1 = fmaf(-2.0f, hi, cn[j]);
                if (d0 < bestv[2 * i])     { bestv[2 * i]     = d0; besti[2 * i]     = ci; }
                if (d1 < bestv[2 * i + 1]) { bestv[2 * i + 1] = d1; besti[2 * i + 1] = ci; }
            }
        }
    }

    // Cross-thread (over ty) argmin reduce, first-min tie-break.
    __syncthreads();
    float* sval = smem;                      // [16][64]
    int*   sidx = (int*)(smem + 16 * 64);    // [16][64]
    #pragma unroll
    for (int t = 0; t < 8; t++) {
        sval[ty * 64 + tx * 8 + t] = bestv[t];
        sidx[ty * 64 + tx * 8 + t] = besti[t];
    }
    __syncthreads();
    if (tid < BT) {
        float bv = sval[tid];
        int   bi = sidx[tid];
        #pragma unroll
        for (int yy = 1; yy < 16; yy++) {
            float v = sval[yy * 64 + tid];
            int  ii = sidx[yy * 64 + tid];
            if (v < bv || (v == bv && ii < bi)) { bv = v; bi = ii; }
        }
        g_token[tok0 + tid] = bi;
    }
}

// ---------------- scatter: counts, embed_sum, quant error ----------------
__global__ void k_scatter(const float* __restrict__ z, const float* __restrict__ w) {
    __shared__ float qs[8];
    int warp = threadIdx.x >> 5;
    int lane = threadIdx.x & 31;
    int n = blockIdx.x * 8 + warp;
    int k = g_token[n];
    float z0 = z[(size_t)n * DDIM + lane];
    float z1 = z[(size_t)n * DDIM + 32 + lane];
    float w0 = w[(size_t)k * DDIM + lane];
    float w1 = w[(size_t)k * DDIM + 32 + lane];
    atomicAdd(&g_embed_sum[k * DDIM + lane], z0);
    atomicAdd(&g_embed_sum[k * DDIM + 32 + lane], z1);
    float d0 = w0 - z0, d1 = w1 - z1;
    float s = d0 * d0 + d1 * d1;
    #pragma unroll
    for (int o = 16; o; o >>= 1) s += __shfl_xor_sync(0xffffffffu, s, o);
    if (lane == 0) { qs[warp] = s; atomicAdd(&g_counts[k], 1.0f); }
    __syncthreads();
    if (threadIdx.x == 0) {
        float t = 0.0f;
        #pragma unroll
        for (int i = 0; i < 8; i++) t += qs[i];
        atomicAdd(&g_qerr, t);
    }
}

// ---------------- EMA stage 1: cluster size + n sum ----------------
__global__ void k_ema1(const float* __restrict__ cs, float* __restrict__ out) {
    __shared__ float red[256];
    int k = blockIdx.x * blockDim.x + threadIdx.x;
    float ncs = cs[k] * DECAYF + (1.0f - DECAYF) * g_counts[k];
    out[1 + KCB * DDIM + k] = ncs;
    red[threadIdx.x] = ncs;
    __syncthreads();
    for (int s = 128; s; s >>= 1) {
        if (threadIdx.x < s) red[threadIdx.x] += red[threadIdx.x + s];
        __syncthreads();
    }
    if (threadIdx.x == 0) atomicAdd(&g_nsum, red[0]);
}

// ---------------- EMA stage 2: embed_avg, weight refresh, qerr ----------------
__global__ void k_ema2(const float* __restrict__ ea, float* __restrict__ out) {
    int i = blockIdx.x * blockDim.x + threadIdx.x;
    if (i < KCB * DDIM) {
        float nea = ea[i] * DECAYF + (1.0f - DECAYF) * g_embed_sum[i];
        out[1 + KCB * DDIM + KCB + i] = nea;      // new_embed_avg
        int k = i >> 6;
        float ncs = out[1 + KCB * DDIM + k];
        float n = g_nsum;
        float smoothed = (ncs + EPSF) / (n + (float)KCB * EPSF) * n;
        out[1 + i] = nea / smoothed;              // new_weight
    }
    if (i == 0) out[0] = g_qerr / (float)NTOK;    // quant_error
}

extern "C" void kernel_launch(void* const* d_in, const int* in_sizes, int n_in,
                              void* d_out, int out_size) {
    const float* z  = (const float*)d_in[0];
    const float* w  = (const float*)d_in[1];
    const float* cs = (const float*)d_in[2];
    const float* ea = (const float*)d_in[3];
    float* out = (float*)d_out;

    cudaFuncSetAttribute(k_main, cudaFuncAttributeMaxDynamicSharedMemorySize, SMEM_MAIN);

    k_zero<<<(KCB * DDIM + 255) / 256, 256>>>();
    k_cnorm<<<KCB / 8, 256>>>(w);
    k_main<<<NTOK / BT, TPB, SMEM_MAIN>>>(z, w);
    k_scatter<<<NTOK / 8, 256>>>(z, w);
    k_ema1<<<KCB / 256, 256>>>(cs, out);
    k_ema2<<<(KCB * DDIM + 255) / 256, 256>>>(ea, out);
}

// round 5
// speedup vs baseline: 4.7003x; 4.7003x over previous
#include <cuda_runtime.h>
#include <cstdint>

#define NTOK 65536
#define KCB  8192
#define DDIM 64
#define DECAYF 0.9f
#define EPSF 1e-5f

// ---- scratch (no allocation allowed) ----
__device__ float g_cnorm[KCB];
__device__ int   g_token[NTOK];
__device__ float g_counts[KCB];
__device__ float g_embed_sum[KCB * DDIM];
__device__ float g_qerr;
__device__ float g_nsum;
// transposed split codebook: rows 0-63 = tf32_hi(w[:,d]), rows 64-127 = tf32_lo
__device__ __align__(16) float g_w3t[(size_t)128 * KCB];

// ================= helpers =================
__device__ __forceinline__ uint32_t smem_u32(const void* p) {
    uint32_t a;
    asm("{ .reg .u64 t; cvta.to.shared.u64 t, %1; cvt.u32.u64 %0, t; }" : "=r"(a) : "l"(p));
    return a;
}
__device__ __forceinline__ uint32_t tf32r(float x) {
    uint32_t u; asm("cvt.rna.tf32.f32 %0, %1;" : "=r"(u) : "f"(x)); return u;
}
__device__ __forceinline__ void cp16(uint32_t dst, const void* src) {
    asm volatile("cp.async.ca.shared.global [%0], [%1], 16;" :: "r"(dst), "l"(src));
}
__device__ __forceinline__ void mma8(float* c, const uint32_t* a, uint32_t b0, uint32_t b1) {
    asm volatile("mma.sync.aligned.m16n8k8.row.col.f32.tf32.tf32.f32 "
        "{%0,%1,%2,%3},{%4,%5,%6,%7},{%8,%9},{%0,%1,%2,%3};"
        : "+f"(c[0]), "+f"(c[1]), "+f"(c[2]), "+f"(c[3])
        : "r"(a[0]), "r"(a[1]), "r"(a[2]), "r"(a[3]), "r"(b0), "r"(b1));
}

// ================= small kernels =================
__global__ void k_zero() {
    int i = blockIdx.x * blockDim.x + threadIdx.x;
    if (i < KCB * DDIM) g_embed_sum[i] = 0.0f;
    if (i < KCB)        g_counts[i]    = 0.0f;
    if (i == 0) { g_qerr = 0.0f; g_nsum = 0.0f; }
}

__global__ void k_cnorm(const float* __restrict__ w) {
    int warp = (blockIdx.x * blockDim.x + threadIdx.x) >> 5;
    int lane = threadIdx.x & 31;
    if (warp >= KCB) return;
    float v0 = w[warp * DDIM + lane];
    float v1 = w[warp * DDIM + 32 + lane];
    float s = v0 * v0 + v1 * v1;
    #pragma unroll
    for (int o = 16; o; o >>= 1) s += __shfl_xor_sync(0xffffffffu, s, o);
    if (lane == 0) g_cnorm[warp] = s;
}

// build g_w3t[k][c]: k<64 -> tf32_hi(w[c][k]); k>=64 -> tf32_lo(w[c][k-64])
__global__ void k_prep(const float* __restrict__ w) {
    int i = blockIdx.x * blockDim.x + threadIdx.x;
    if (i >= 128 * KCB) return;
    int k = i >> 13, c = i & (KCB - 1);
    float v = w[(size_t)c * DDIM + (k & 63)];
    uint32_t hi = tf32r(v);
    uint32_t out = (k < 64) ? hi : tf32r(v - __uint_as_float(hi));
    ((uint32_t*)g_w3t)[i] = out;
}

// ================= main tensor-core kernel (mma.sync tf32, 3xTF32) =================
static constexpr int A_STRIDE = 132;                 // floats; bank = 4*row + col
static constexpr int B_STRIDE = 72;                  // floats; bank = 8*k + n
static constexpr int SM_A  = 0;                      // 128*132*4 = 67584
static constexpr int SM_B  = 67584;                  // 2 * 128*72*4 = 73728
static constexpr int B_BUF = 128 * B_STRIDE * 4;     // 36864
static constexpr int SM_CN = SM_B + 2 * B_BUF;       // 141312
static constexpr int SMEM_TC = SM_CN + KCB * 4;      // 174080

__global__ __launch_bounds__(256, 1) void k_main_tc(const float* __restrict__ z) {
    extern __shared__ char smem[];
    float* As = (float*)(smem + SM_A);
    float* Bs = (float*)(smem + SM_B);
    float* CN = (float*)(smem + SM_CN);
    const uint32_t sbB = smem_u32(Bs);

    const int tid  = threadIdx.x;
    const int lane = tid & 31, wid = tid >> 5;
    const int g    = lane >> 2, tg = lane & 3;
    const int wr   = wid & 3,  wc = wid >> 2;       // warp row (tokens), warp col (codes)
    const int tok0 = blockIdx.x * 128;

    // ---- load all ||c||^2 into smem (32 KB) ----
    #pragma unroll
    for (int i = 0; i < 8; i++) {
        int q = i * 256 + tid;
        *(float4*)(CN + q * 4) = *(const float4*)(g_cnorm + q * 4);
    }
    // ---- stage A: z[128][64] -> hi cols 0-63, lo cols 64-127 ----
    #pragma unroll
    for (int i = 0; i < 8; i++) {
        int q = i * 256 + tid;                       // 2048 float4 total
        int row = q >> 4, c4 = q & 15;
        float4 v = *(const float4*)(z + (size_t)(tok0 + row) * DDIM + c4 * 4);
        float4 hi, lo;
        hi.x = __uint_as_float(tf32r(v.x)); lo.x = __uint_as_float(tf32r(v.x - hi.x));
        hi.y = __uint_as_float(tf32r(v.y)); lo.y = __uint_as_float(tf32r(v.y - hi.y));
        hi.z = __uint_as_float(tf32r(v.z)); lo.z = __uint_as_float(tf32r(v.z - hi.z));
        hi.w = __uint_as_float(tf32r(v.w)); lo.w = __uint_as_float(tf32r(v.w - hi.w));
        *(float4*)(As + row * A_STRIDE + c4 * 4)      = hi;
        *(float4*)(As + row * A_STRIDE + 64 + c4 * 4) = lo;
    }
    // ---- prefetch B tile 0 (cb=0) into buf 0 ----
    #pragma unroll
    for (int i = 0; i < 8; i++) {
        int q = i * 256 + tid;                       // 2048 chunks of 16B
        int k = q >> 4, seg = q & 15;
        cp16(sbB + (uint32_t)(k * B_STRIDE + seg * 4) * 4,
             g_w3t + (size_t)k * KCB + seg * 4);
    }
    asm volatile("cp.async.commit_group;");
    __syncthreads();

    float bv[4];  int bix[4];
    #pragma unroll
    for (int r = 0; r < 4; r++) { bv[r] = 3.4e38f; bix[r] = 0; }

    for (int t = 0; t < 128; t++) {
        const int buf = t & 1;
        if (t < 127) {
            const int cb1 = (t + 1) * 64;
            const uint32_t dstb = sbB + (uint32_t)(buf ^ 1) * B_BUF;
            #pragma unroll
            for (int i = 0; i < 8; i++) {
                int q = i * 256 + tid;
                int k = q >> 4, seg = q & 15;
                cp16(dstb + (uint32_t)(k * B_STRIDE + seg * 4) * 4,
                     g_w3t + (size_t)k * KCB + cb1 + seg * 4);
            }
            asm volatile("cp.async.commit_group;");
            asm volatile("cp.async.wait_group 1;");
        } else {
            asm volatile("cp.async.wait_group 0;");
        }
        __syncthreads();

        const float* B = Bs + buf * (128 * B_STRIDE);
        float acc[2][4][4];
        #pragma unroll
        for (int m = 0; m < 2; m++)
            #pragma unroll
            for (int nt = 0; nt < 4; nt++)
                #pragma unroll
                for (int c = 0; c < 4; c++) acc[m][nt][c] = 0.0f;

        #pragma unroll
        for (int s = 0; s < 24; s++) {
            const int ca = (s < 8) ? 8 * s : 8 * s - 64;   // A col base (hi,hi,lo)
            const int kb = (8 * s) & 127;                  // B row base (hi,lo,hi)
            uint32_t a[2][4];
            #pragma unroll
            for (int m = 0; m < 2; m++) {
                const float* ap = As + (wr * 32 + m * 16 + g) * A_STRIDE + ca + tg;
                a[m][0] = __float_as_uint(ap[0]);
                a[m][1] = __float_as_uint(ap[8 * A_STRIDE]);
                a[m][2] = __float_as_uint(ap[4]);
                a[m][3] = __float_as_uint(ap[8 * A_STRIDE + 4]);
            }
            #pragma unroll
            for (int nt = 0; nt < 4; nt++) {
                const float* bp = B + (kb + tg) * B_STRIDE + wc * 32 + nt * 8 + g;
                uint32_t b0 = __float_as_uint(bp[0]);
                uint32_t b1 = __float_as_uint(bp[4 * B_STRIDE]);
                mma8(acc[0][nt], a[0], b0, b1);
                mma8(acc[1][nt], a[1], b0, b1);
            }
        }

        // epilogue: dist = cn - 2*dot, per-thread running argmin (ascending cols)
        const int cb = t * 64;
        #pragma unroll
        for (int nt = 0; nt < 4; nt++) {
            const int col = cb + wc * 32 + nt * 8 + 2 * tg;
            const float cn0 = CN[col], cn1 = CN[col + 1];
            #pragma unroll
            for (int m = 0; m < 2; m++) {
                #pragma unroll
                for (int h = 0; h < 2; h++) {
                    const int r = m * 2 + h;
                    float d0 = fmaf(-2.0f, acc[m][nt][h * 2 + 0], cn0);
                    float d1 = fmaf(-2.0f, acc[m][nt][h * 2 + 1], cn1);
                    if (d0 < bv[r]) { bv[r] = d0; bix[r] = col; }
                    if (d1 < bv[r]) { bv[r] = d1; bix[r] = col + 1; }
                }
            }
        }
        __syncthreads();
    }

    // combine across quad lanes (same rows), tie-break on smaller index
    #pragma unroll
    for (int r = 0; r < 4; r++) {
        float v = bv[r]; int ix = bix[r];
        #pragma unroll
        for (int o = 1; o < 4; o <<= 1) {
            float v2 = __shfl_xor_sync(0xffffffffu, v, o);
            int   i2 = __shfl_xor_sync(0xffffffffu, ix, o);
            if (v2 < v || (v2 == v && i2 < ix)) { v = v2; ix = i2; }
        }
        bv[r] = v; bix[r] = ix;
    }
    __syncthreads();
    float* sv = Bs;                 // reuse B buffer as scratch
    int*   si = (int*)(Bs + 256);
    if (tg == 0) {
        #pragma unroll
        for (int m = 0; m < 2; m++)
            #pragma unroll
            for (int h = 0; h < 2; h++) {
                int row = wr * 32 + m * 16 + g + 8 * h;
                sv[wc * 128 + row] = bv[m * 2 + h];
                si[wc * 128 + row] = bix[m * 2 + h];
            }
    }
    __syncthreads();
    if (tid < 128) {
        float v0 = sv[tid], v1 = sv[128 + tid];
        int   i0 = si[tid], i1 = si[128 + tid];
        g_token[tok0 + tid] = (v1 < v0 || (v1 == v0 && i1 < i0)) ? i1 : i0;
    }
}

// ---------------- scatter: counts, embed_sum, quant error ----------------
__global__ void k_scatter(const float* __restrict__ z, const float* __restrict__ w) {
    __shared__ float qs[8];
    int warp = threadIdx.x >> 5;
    int lane = threadIdx.x & 31;
    int n = blockIdx.x * 8 + warp;
    int k = g_token[n];
    float z0 = z[(size_t)n * DDIM + lane];
    float z1 = z[(size_t)n * DDIM + 32 + lane];
    float w0 = w[(size_t)k * DDIM + lane];
    float w1 = w[(size_t)k * DDIM + 32 + lane];
    atomicAdd(&g_embed_sum[k * DDIM + lane], z0);
    atomicAdd(&g_embed_sum[k * DDIM + 32 + lane], z1);
    float d0 = w0 - z0, d1 = w1 - z1;
    float s = d0 * d0 + d1 * d1;
    #pragma unroll
    for (int o = 16; o; o >>= 1) s += __shfl_xor_sync(0xffffffffu, s, o);
    if (lane == 0) { qs[warp] = s; atomicAdd(&g_counts[k], 1.0f); }
    __syncthreads();
    if (threadIdx.x == 0) {
        float t = 0.0f;
        #pragma unroll
        for (int i = 0; i < 8; i++) t += qs[i];
        atomicAdd(&g_qerr, t);
    }
}

__global__ void k_ema1(const float* __restrict__ cs, float* __restrict__ out) {
    __shared__ float red[256];
    int k = blockIdx.x * blockDim.x + threadIdx.x;
    float ncs = cs[k] * DECAYF + (1.0f - DECAYF) * g_counts[k];
    out[1 + KCB * DDIM + k] = ncs;
    red[threadIdx.x] = ncs;
    __syncthreads();
    for (int s = 128; s; s >>= 1) {
        if (threadIdx.x < s) red[threadIdx.x] += red[threadIdx.x + s];
        __syncthreads();
    }
    if (threadIdx.x == 0) atomicAdd(&g_nsum, red[0]);
}

__global__ void k_ema2(const float* __restrict__ ea, float* __restrict__ out) {
    int i = blockIdx.x * blockDim.x + threadIdx.x;
    if (i < KCB * DDIM) {
        float nea = ea[i] * DECAYF + (1.0f - DECAYF) * g_embed_sum[i];
        out[1 + KCB * DDIM + KCB + i] = nea;
        int k = i >> 6;
        float ncs = out[1 + KCB * DDIM + k];
        float n = g_nsum;
        float smoothed = (ncs + EPSF) / (n + (float)KCB * EPSF) * n;
        out[1 + i] = nea / smoothed;
    }
    if (i == 0) out[0] = g_qerr / (float)NTOK;
}

extern "C" void kernel_launch(void* const* d_in, const int* in_sizes, int n_in,
                              void* d_out, int out_size) {
    const float* z  = (const float*)d_in[0];
    const float* w  = (const float*)d_in[1];
    const float* cs = (const float*)d_in[2];
    const float* ea = (const float*)d_in[3];
    float* out = (float*)d_out;

    cudaFuncSetAttribute(k_main_tc, cudaFuncAttributeMaxDynamicSharedMemorySize, SMEM_TC);

    k_zero<<<(KCB * DDIM + 255) / 256, 256>>>();
    k_cnorm<<<KCB / 8, 256>>>(w);
    k_prep<<<(128 * KCB + 255) / 256, 256>>>(w);
    k_main_tc<<<NTOK / 128, 256, SMEM_TC>>>(z);
    k_scatter<<<NTOK / 8, 256>>>(z, w);
    k_ema1<<<KCB / 256, 256>>>(cs, out);
    k_ema2<<<(KCB * DDIM + 255) / 256, 256>>>(ea, out);
}